// round 11
// baseline (speedup 1.0000x reference)
#include <cuda_runtime.h>
#include <cuda_bf16.h>
#include <cstdint>
#include <math.h>

// Problem shape (fixed by the reference).
#define B_ 8
#define T_ 2048
#define C_ 1024
#define H_ 128
#define M_ (B_ * T_)

// Scratch (no cudaMalloc -> __device__ globals).
__device__ __align__(16) __nv_bfloat16 g_qh[(size_t)M_ * H_];
__device__ __align__(16) __nv_bfloat16 g_ql[(size_t)M_ * H_];
__device__ __align__(16) __nv_bfloat16 g_kh[(size_t)M_ * H_];
__device__ __align__(16) __nv_bfloat16 g_kl[(size_t)M_ * H_];
__device__ __align__(16) __nv_bfloat16 g_vh[(size_t)M_ * H_];
__device__ __align__(16) __nv_bfloat16 g_vl[(size_t)M_ * H_];
__device__ __align__(16) __nv_bfloat16 g_wt[6][128 * 1024];

__device__ __forceinline__ uint32_t pack_bf16(float a, float b) {
    __nv_bfloat162 t = __halves2bfloat162(__float2bfloat16(a), __float2bfloat16(b));
    return *(uint32_t*)&t;
}

__device__ __forceinline__ void mma16816(float* d, const uint32_t* a,
                                         const uint32_t* b) {
    asm volatile(
        "mma.sync.aligned.m16n8k16.row.col.f32.bf16.bf16.f32 "
        "{%0,%1,%2,%3}, {%4,%5,%6,%7}, {%8,%9}, {%0,%1,%2,%3};"
        : "+f"(d[0]), "+f"(d[1]), "+f"(d[2]), "+f"(d[3])
        : "r"(a[0]), "r"(a[1]), "r"(a[2]), "r"(a[3]), "r"(b[0]), "r"(b[1]));
}

__device__ __forceinline__ uint32_t cvta_sm(const void* p) {
    uint32_t a;
    asm("{ .reg .u64 t; cvta.to.shared.u64 t, %1; cvt.u32.u64 %0, t; }"
        : "=r"(a) : "l"(p));
    return a;
}
#define LDSM_X4(r0, r1, r2, r3, a)                                        \
    asm volatile("ldmatrix.sync.aligned.m8n8.x4.shared.b16 "              \
                 "{%0,%1,%2,%3}, [%4];"                                   \
                 : "=r"(r0), "=r"(r1), "=r"(r2), "=r"(r3) : "r"(a))
#define LDSM_X4_T(r0, r1, r2, r3, a)                                      \
    asm volatile("ldmatrix.sync.aligned.m8n8.x4.trans.shared.b16 "        \
                 "{%0,%1,%2,%3}, [%4];"                                   \
                 : "=r"(r0), "=r"(r1), "=r"(r2), "=r"(r3) : "r"(a))
#define CP16(dst, src)                                                    \
    asm volatile("cp.async.cg.shared.global [%0], [%1], 16;"              \
                 :: "r"(dst), "l"(src))
#define CP_COMMIT() asm volatile("cp.async.commit_group;" ::: "memory")
#define CP_WAIT1()  asm volatile("cp.async.wait_group 1;"  ::: "memory")

// ---------------------------------------------------------------------------
// Kernel 0: split + transpose weights into bf16 hi/lo, K-major [n][k].
// ---------------------------------------------------------------------------
__global__ __launch_bounds__(256) void wsplit_kernel(
    const float* __restrict__ Wk, const float* __restrict__ Wq,
    const float* __restrict__ Wv)
{
    int o = blockIdx.y;
    const float* W = (o == 0) ? Wk : (o == 1) ? Wq : Wv;
    int idx = blockIdx.x * 256 + threadIdx.x;
    int n = idx >> 10, k = idx & 1023;
    float v = W[(size_t)k * H_ + n];
    __nv_bfloat16 hi = __float2bfloat16(v);
    float lo = v - __bfloat162float(hi);
    g_wt[o * 2 + 0][idx] = hi;
    g_wt[o * 2 + 1][idx] = __float2bfloat16(lo);
}

// ---------------------------------------------------------------------------
// Kernel 1: QKV projection via mma.sync (bf16, fp32 accum), 3-term split.
// Fragments now via ldmatrix.x4 (same addressing class proven in attn).
// ---------------------------------------------------------------------------
#define AST 72
#define A_HI_OFF 0
#define A_LO_OFF (128 * AST * 2)
#define B_HI_OFF (2 * 128 * AST * 2)
#define B_LO_OFF (3 * 128 * AST * 2)
#define PROJ_SMEM (4 * 128 * AST * 2)

__global__ __launch_bounds__(256) void proj_mma_kernel(const float* __restrict__ x)
{
    extern __shared__ __align__(16) char smem[];
    const uint32_t sbm = cvta_sm(smem);
    const int tid  = threadIdx.x;
    const int wid  = tid >> 5;
    const int lane = tid & 31;
    const int wm   = wid >> 2;
    const int wn   = wid & 3;
    const int g    = lane >> 2;
    const int q    = lane & 3;
    const int row0 = blockIdx.x * 128;
    const int o    = blockIdx.y;

    const __nv_bfloat16* wt_hi = g_wt[o * 2 + 0];
    const __nv_bfloat16* wt_lo = g_wt[o * 2 + 1];

    // ldmatrix per-thread address component (row = lane&15, col-half = lane>>4).
    const uint32_t lm = (uint32_t)((lane & 15) * (AST * 2) + (lane >> 4) * 16);

    float acc[4][4][4];
#pragma unroll
    for (int m = 0; m < 4; m++)
#pragma unroll
        for (int n = 0; n < 4; n++)
#pragma unroll
            for (int r = 0; r < 4; r++) acc[m][n][r] = 0.f;

    for (int s = 0; s < 16; s++) {
        const int k0 = s * 64;
        __syncthreads();

#pragma unroll
        for (int i = 0; i < 8; i++) {
            int u = tid + 256 * i;
            int r = u >> 4, gg = u & 15;
            float4 f = *(const float4*)(x + (size_t)(row0 + r) * C_ + k0 + gg * 4);
            __nv_bfloat16 h0 = __float2bfloat16(f.x);
            __nv_bfloat16 h1 = __float2bfloat16(f.y);
            __nv_bfloat16 h2 = __float2bfloat16(f.z);
            __nv_bfloat16 h3 = __float2bfloat16(f.w);
            __nv_bfloat162 hA = __halves2bfloat162(h0, h1);
            __nv_bfloat162 hB = __halves2bfloat162(h2, h3);
            __nv_bfloat162 lA = __halves2bfloat162(
                __float2bfloat16(f.x - __bfloat162float(h0)),
                __float2bfloat16(f.y - __bfloat162float(h1)));
            __nv_bfloat162 lB = __halves2bfloat162(
                __float2bfloat16(f.z - __bfloat162float(h2)),
                __float2bfloat16(f.w - __bfloat162float(h3)));
            uint32_t off = (uint32_t)(r * (AST * 2) + gg * 8);
            *(uint2*)(smem + A_HI_OFF + off) =
                make_uint2(*(uint32_t*)&hA, *(uint32_t*)&hB);
            *(uint2*)(smem + A_LO_OFF + off) =
                make_uint2(*(uint32_t*)&lA, *(uint32_t*)&lB);
        }
#pragma unroll
        for (int i = 0; i < 8; i++) {
            int u = tid + 256 * i;
            int t = u >> 10;
            int w = u & 1023;
            int n = w >> 3, gg = w & 7;
            const __nv_bfloat16* src = (t == 0) ? wt_hi : wt_lo;
            uint4 v = *(const uint4*)(src + (size_t)n * C_ + k0 + gg * 8);
            uint32_t off = (uint32_t)(n * (AST * 2) + gg * 16);
            char* dst = smem + ((t == 0) ? B_HI_OFF : B_LO_OFF) + off;
            *(uint2*)(dst + 0) = make_uint2(v.x, v.y);
            *(uint2*)(dst + 8) = make_uint2(v.z, v.w);
        }
        __syncthreads();

#pragma unroll
        for (int p = 0; p < 3; p++) {
            const uint32_t aoff =
                sbm + ((p == 2) ? A_LO_OFF : A_HI_OFF) +
                (uint32_t)(wm * 64 * (AST * 2)) + lm;
            const uint32_t boff =
                sbm + ((p == 1) ? B_LO_OFF : B_HI_OFF) +
                (uint32_t)(wn * 32 * (AST * 2)) + lm;
#pragma unroll
            for (int kk = 0; kk < 4; kk++) {
                uint32_t af[4][4];
#pragma unroll
                for (int m = 0; m < 4; m++)
                    LDSM_X4(af[m][0], af[m][1], af[m][2], af[m][3],
                            aoff + (uint32_t)(m * 16 * (AST * 2)) + kk * 32);
                uint32_t bf[4][2];
#pragma unroll
                for (int nq = 0; nq < 2; nq++) {
                    uint32_t r0, r1, r2, r3;
                    LDSM_X4(r0, r1, r2, r3,
                            boff + (uint32_t)(nq * 16 * (AST * 2)) + kk * 32);
                    bf[nq * 2][0] = r0;     bf[nq * 2][1] = r2;
                    bf[nq * 2 + 1][0] = r1; bf[nq * 2 + 1][1] = r3;
                }
#pragma unroll
                for (int m = 0; m < 4; m++)
#pragma unroll
                    for (int n = 0; n < 4; n++)
                        mma16816(acc[m][n], af[m], bf[n]);
            }
        }
    }

    const float sc = (o == 1) ? 0.03125f : 1.0f;
    __nv_bfloat16* dh = (o == 0) ? g_kh : (o == 1) ? g_qh : g_vh;
    __nv_bfloat16* dl = (o == 0) ? g_kl : (o == 1) ? g_ql : g_vl;
#pragma unroll
    for (int m = 0; m < 4; m++) {
        int r0 = row0 + wm * 64 + m * 16 + g;
#pragma unroll
        for (int n = 0; n < 4; n++) {
            int col = wn * 32 + n * 8 + q * 2;
            float v0 = acc[m][n][0] * sc, v1 = acc[m][n][1] * sc;
            float v2 = acc[m][n][2] * sc, v3 = acc[m][n][3] * sc;
            __nv_bfloat16 h0 = __float2bfloat16(v0), h1 = __float2bfloat16(v1);
            __nv_bfloat16 h2 = __float2bfloat16(v2), h3 = __float2bfloat16(v3);
            *(uint32_t*)(dh + (size_t)r0 * H_ + col) =
                pack_bf16(__bfloat162float(h0), __bfloat162float(h1));
            *(uint32_t*)(dl + (size_t)r0 * H_ + col) =
                pack_bf16(v0 - __bfloat162float(h0), v1 - __bfloat162float(h1));
            *(uint32_t*)(dh + (size_t)(r0 + 8) * H_ + col) =
                pack_bf16(__bfloat162float(h2), __bfloat162float(h3));
            *(uint32_t*)(dl + (size_t)(r0 + 8) * H_ + col) =
                pack_bf16(v2 - __bfloat162float(h2), v3 - __bfloat162float(h3));
        }
    }
}

// ---------------------------------------------------------------------------
// Kernel 2: causal flash attention, paired q-tiles + cp.async double buffer.
// Unchanged from R10 (passing, 153us).
// ---------------------------------------------------------------------------
#define QKS 272
#define TSZ (64 * QKS)
#define QBH_OFF 0
#define QBL_OFF (1 * TSZ)
#define QAH_OFF (2 * TSZ)
#define QAL_OFF (3 * TSZ)
#define KV0_OFF (4 * TSZ)
#define ATTN_SMEM (12 * TSZ)    // 208896 B

__global__ __launch_bounds__(256) void attn_mma_kernel(float* __restrict__ out)
{
    extern __shared__ __align__(16) char smem[];
    const uint32_t sb = cvta_sm(smem);
    const int tid  = threadIdx.x;
    const int w    = tid >> 5;
    const int wg   = w >> 2;
    const int wl   = w & 3;
    const int lane = tid & 31;
    const int g    = lane >> 2;
    const int q4   = lane & 3;

    const int b   = blockIdx.x >> 4;
    const int p   = blockIdx.x & 15;
    const int qtB = 31 - p;
    const int qt_own = wg ? p : qtB;
    const int q0_own = qt_own * 64;
    const int bT  = b * T_;

    const uint32_t lm_off = (uint32_t)((lane & 15) * QKS + (lane >> 4) * 16);

#pragma unroll
    for (int i = 0; i < 8; i++) {
        int u = tid + 256 * i;
        int t = u >> 10;
        int rem = u & 1023;
        int r = rem >> 4, c = rem & 15;
        int qrow = (t == 0 ? qtB : p) * 64 + r;
        size_t src = (size_t)(bT + qrow) * H_ + c * 8;
        uint32_t dst = (uint32_t)(t * 2 * TSZ + r * QKS + c * 16);
        *(uint4*)(smem + QBH_OFF + dst) = *(const uint4*)(g_qh + src);
        *(uint4*)(smem + QBL_OFF + dst) = *(const uint4*)(g_ql + src);
    }

    {
        uint32_t dstb = sb + KV0_OFF;
#pragma unroll
        for (int i = 0; i < 4; i++) {
            int u = tid + 256 * i;
            int r = u >> 4, c = u & 15;
            size_t src = (size_t)(bT + r) * H_ + c * 8;
            uint32_t d0 = dstb + (uint32_t)(r * QKS + c * 16);
            CP16(d0 + 0 * TSZ, g_kh + src);
            CP16(d0 + 1 * TSZ, g_kl + src);
            CP16(d0 + 2 * TSZ, g_vh + src);
            CP16(d0 + 3 * TSZ, g_vl + src);
        }
        CP_COMMIT();
    }

    float oacc[16][4];
#pragma unroll
    for (int n = 0; n < 16; n++)
#pragma unroll
        for (int r = 0; r < 4; r++) oacc[n][r] = 0.f;
    float m0 = -1e30f, m1 = -1e30f, l0 = 0.f, l1 = 0.f;

    for (int j = 0; j <= qtB; j++) {
        __syncthreads();

        if (j + 1 <= qtB) {
            const int kvn = (j + 1) * 64;
            uint32_t dstb = sb + KV0_OFF + (uint32_t)(((j + 1) & 1) * 4 * TSZ);
#pragma unroll
            for (int i = 0; i < 4; i++) {
                int u = tid + 256 * i;
                int r = u >> 4, c = u & 15;
                size_t src = (size_t)(bT + kvn + r) * H_ + c * 8;
                uint32_t d0 = dstb + (uint32_t)(r * QKS + c * 16);
                CP16(d0 + 0 * TSZ, g_kh + src);
                CP16(d0 + 1 * TSZ, g_kl + src);
                CP16(d0 + 2 * TSZ, g_vh + src);
                CP16(d0 + 3 * TSZ, g_vl + src);
            }
        }
        CP_COMMIT();
        CP_WAIT1();
        __syncthreads();

        if (wg == 1 && j > p) continue;

        const uint32_t kvb = (uint32_t)(KV0_OFF + (j & 1) * 4 * TSZ);
        const uint32_t qh_off = wg ? QAH_OFF : QBH_OFF;
        const uint32_t ql_off = wg ? QAL_OFF : QBL_OFF;

        float sacc[8][4];
#pragma unroll
        for (int n = 0; n < 8; n++)
#pragma unroll
            for (int r = 0; r < 4; r++) sacc[n][r] = 0.f;

        const uint32_t qrow_off = (uint32_t)(wl * 16 * QKS);
#pragma unroll
        for (int ps = 0; ps < 3; ps++) {
            const uint32_t qb = sb + ((ps == 2) ? ql_off : qh_off) + qrow_off + lm_off;
            const uint32_t kb = sb + kvb + ((ps == 1) ? TSZ : 0) + lm_off;
#pragma unroll
            for (int kt = 0; kt < 8; kt++) {
                uint32_t a[4];
                LDSM_X4(a[0], a[1], a[2], a[3], qb + kt * 32);
#pragma unroll
                for (int nq = 0; nq < 4; nq++) {
                    uint32_t r0, r1, r2, r3;
                    LDSM_X4(r0, r1, r2, r3, kb + nq * 16 * QKS + kt * 32);
                    uint32_t b0[2] = {r0, r2}, b1[2] = {r1, r3};
                    mma16816(sacc[nq * 2], a, b0);
                    mma16816(sacc[nq * 2 + 1], a, b1);
                }
            }
        }

        if (j == qt_own) {
            int rl0 = wl * 16 + g, rl1 = rl0 + 8;
#pragma unroll
            for (int n = 0; n < 8; n++) {
                int cb = n * 8 + q4 * 2;
                if (cb     > rl0) sacc[n][0] = -1e30f;
                if (cb + 1 > rl0) sacc[n][1] = -1e30f;
                if (cb     > rl1) sacc[n][2] = -1e30f;
                if (cb + 1 > rl1) sacc[n][3] = -1e30f;
            }
        }

        float mx0 = -1e30f, mx1 = -1e30f;
#pragma unroll
        for (int n = 0; n < 8; n++) {
            mx0 = fmaxf(mx0, fmaxf(sacc[n][0], sacc[n][1]));
            mx1 = fmaxf(mx1, fmaxf(sacc[n][2], sacc[n][3]));
        }
        mx0 = fmaxf(mx0, __shfl_xor_sync(0xffffffffu, mx0, 1));
        mx0 = fmaxf(mx0, __shfl_xor_sync(0xffffffffu, mx0, 2));
        mx1 = fmaxf(mx1, __shfl_xor_sync(0xffffffffu, mx1, 1));
        mx1 = fmaxf(mx1, __shfl_xor_sync(0xffffffffu, mx1, 2));
        float mn0 = fmaxf(m0, mx0), mn1 = fmaxf(m1, mx1);
        float c0 = __expf(m0 - mn0), c1 = __expf(m1 - mn1);
        m0 = mn0; m1 = mn1;

        uint32_t ph[8][2], pl[8][2];
        float s0 = 0.f, s1 = 0.f;
#pragma unroll
        for (int n = 0; n < 8; n++) {
            float p00 = __expf(sacc[n][0] - mn0);
            float p01 = __expf(sacc[n][1] - mn0);
            float p10 = __expf(sacc[n][2] - mn1);
            float p11 = __expf(sacc[n][3] - mn1);
            s0 += p00 + p01; s1 += p10 + p11;
            __nv_bfloat16 h00 = __float2bfloat16(p00);
            __nv_bfloat16 h01 = __float2bfloat16(p01);
            __nv_bfloat16 h10 = __float2bfloat16(p10);
            __nv_bfloat16 h11 = __float2bfloat16(p11);
            ph[n][0] = pack_bf16(__bfloat162float(h00), __bfloat162float(h01));
            ph[n][1] = pack_bf16(__bfloat162float(h10), __bfloat162float(h11));
            pl[n][0] = pack_bf16(p00 - __bfloat162float(h00),
                                 p01 - __bfloat162float(h01));
            pl[n][1] = pack_bf16(p10 - __bfloat162float(h10),
                                 p11 - __bfloat162float(h11));
        }
        s0 += __shfl_xor_sync(0xffffffffu, s0, 1);
        s0 += __shfl_xor_sync(0xffffffffu, s0, 2);
        s1 += __shfl_xor_sync(0xffffffffu, s1, 1);
        s1 += __shfl_xor_sync(0xffffffffu, s1, 2);
        l0 = l0 * c0 + s0;
        l1 = l1 * c1 + s1;
#pragma unroll
        for (int n = 0; n < 16; n++) {
            oacc[n][0] *= c0; oacc[n][1] *= c0;
            oacc[n][2] *= c1; oacc[n][3] *= c1;
        }

#pragma unroll
        for (int ps = 0; ps < 3; ps++) {
            const uint32_t vb = sb + kvb + ((ps == 1) ? 3 : 2) * TSZ + lm_off;
            const uint32_t (*P)[2] = (ps == 2) ? pl : ph;
#pragma unroll
            for (int kt = 0; kt < 4; kt++) {
                uint32_t a[4];
                a[0] = P[2 * kt][0];
                a[1] = P[2 * kt][1];
                a[2] = P[2 * kt + 1][0];
                a[3] = P[2 * kt + 1][1];
#pragma unroll
                for (int np = 0; np < 8; np++) {
                    uint32_t r0, r1, r2, r3;
                    LDSM_X4_T(r0, r1, r2, r3,
                              vb + (uint32_t)(kt * 16 * QKS) + np * 32);
                    uint32_t b0[2] = {r0, r1}, b1[2] = {r2, r3};
                    mma16816(oacc[np * 2], a, b0);
                    mma16816(oacc[np * 2 + 1], a, b1);
                }
            }
        }
    }

    float i0 = 1.f / l0, i1 = 1.f / l1;
    size_t rbase = (size_t)(bT + q0_own + wl * 16 + g);
#pragma unroll
    for (int n = 0; n < 16; n++) {
        int col = n * 8 + q4 * 2;
        *(float2*)(out + rbase * H_ + col) =
            make_float2(oacc[n][0] * i0, oacc[n][1] * i0);
        *(float2*)(out + (rbase + 8) * H_ + col) =
            make_float2(oacc[n][2] * i1, oacc[n][3] * i1);
    }
}

// ---------------------------------------------------------------------------
extern "C" void kernel_launch(void* const* d_in, const int* in_sizes, int n_in,
                              void* d_out, int out_size)
{
    const float* x  = (const float*)d_in[0];
    const float* Wk = (const float*)d_in[1];
    const float* Wq = (const float*)d_in[2];
    const float* Wv = (const float*)d_in[3];
    float* out = (float*)d_out;

    cudaFuncSetAttribute(proj_mma_kernel,
                         cudaFuncAttributeMaxDynamicSharedMemorySize, PROJ_SMEM);
    cudaFuncSetAttribute(attn_mma_kernel,
                         cudaFuncAttributeMaxDynamicSharedMemorySize, ATTN_SMEM);

    wsplit_kernel<<<dim3(512, 3), 256>>>(Wk, Wq, Wv);
    proj_mma_kernel<<<dim3(128, 3), 256, PROJ_SMEM>>>(x);
    attn_mma_kernel<<<128, 256, ATTN_SMEM>>>(out);
}

// round 12
// speedup vs baseline: 1.1852x; 1.1852x over previous
#include <cuda_runtime.h>
#include <cuda_bf16.h>
#include <cstdint>
#include <math.h>

// Problem shape (fixed by the reference).
#define B_ 8
#define T_ 2048
#define C_ 1024
#define H_ 128
#define M_ (B_ * T_)

// Scratch (no cudaMalloc -> __device__ globals).
__device__ __align__(16) __nv_bfloat16 g_qh[(size_t)M_ * H_];
__device__ __align__(16) __nv_bfloat16 g_ql[(size_t)M_ * H_];
__device__ __align__(16) __nv_bfloat16 g_kh[(size_t)M_ * H_];
__device__ __align__(16) __nv_bfloat16 g_kl[(size_t)M_ * H_];
__device__ __align__(16) __nv_bfloat16 g_vh[(size_t)M_ * H_];
__device__ __align__(16) __nv_bfloat16 g_vl[(size_t)M_ * H_];
__device__ __align__(16) __nv_bfloat16 g_wt[6][128 * 1024];

__device__ __forceinline__ uint32_t pack_bf16(float a, float b) {
    __nv_bfloat162 t = __halves2bfloat162(__float2bfloat16(a), __float2bfloat16(b));
    return *(uint32_t*)&t;
}

__device__ __forceinline__ void mma16816(float* d, const uint32_t* a,
                                         const uint32_t* b) {
    asm volatile(
        "mma.sync.aligned.m16n8k16.row.col.f32.bf16.bf16.f32 "
        "{%0,%1,%2,%3}, {%4,%5,%6,%7}, {%8,%9}, {%0,%1,%2,%3};"
        : "+f"(d[0]), "+f"(d[1]), "+f"(d[2]), "+f"(d[3])
        : "r"(a[0]), "r"(a[1]), "r"(a[2]), "r"(a[3]), "r"(b[0]), "r"(b[1]));
}

__device__ __forceinline__ uint32_t cvta_sm(const void* p) {
    uint32_t a;
    asm("{ .reg .u64 t; cvta.to.shared.u64 t, %1; cvt.u32.u64 %0, t; }"
        : "=r"(a) : "l"(p));
    return a;
}
#define LDSM_X4(r0, r1, r2, r3, a)                                        \
    asm volatile("ldmatrix.sync.aligned.m8n8.x4.shared.b16 "              \
                 "{%0,%1,%2,%3}, [%4];"                                   \
                 : "=r"(r0), "=r"(r1), "=r"(r2), "=r"(r3) : "r"(a))
#define LDSM_X4_T(r0, r1, r2, r3, a)                                      \
    asm volatile("ldmatrix.sync.aligned.m8n8.x4.trans.shared.b16 "        \
                 "{%0,%1,%2,%3}, [%4];"                                   \
                 : "=r"(r0), "=r"(r1), "=r"(r2), "=r"(r3) : "r"(a))
#define CP16(dst, src)                                                    \
    asm volatile("cp.async.cg.shared.global [%0], [%1], 16;"              \
                 :: "r"(dst), "l"(src))
#define CP_COMMIT() asm volatile("cp.async.commit_group;" ::: "memory")
#define CP_WAIT1()  asm volatile("cp.async.wait_group 1;"  ::: "memory")
#define BARG(id)                                                          \
    asm volatile("bar.sync %0, %1;" :: "r"(id), "r"(128) : "memory")

// ---------------------------------------------------------------------------
// Kernel 0: split + transpose weights into bf16 hi/lo, K-major [n][k].
// ---------------------------------------------------------------------------
__global__ __launch_bounds__(256) void wsplit_kernel(
    const float* __restrict__ Wk, const float* __restrict__ Wq,
    const float* __restrict__ Wv)
{
    int o = blockIdx.y;
    const float* W = (o == 0) ? Wk : (o == 1) ? Wq : Wv;
    int idx = blockIdx.x * 256 + threadIdx.x;
    int n = idx >> 10, k = idx & 1023;
    float v = W[(size_t)k * H_ + n];
    __nv_bfloat16 hi = __float2bfloat16(v);
    float lo = v - __bfloat162float(hi);
    g_wt[o * 2 + 0][idx] = hi;
    g_wt[o * 2 + 1][idx] = __float2bfloat16(lo);
}

// ---------------------------------------------------------------------------
// Kernel 1: QKV projection (EXACT R10 version: scalar-LDS fragments, proven).
// ---------------------------------------------------------------------------
#define AST 72
#define A_HI_OFF 0
#define A_LO_OFF (128 * AST * 2)
#define B_HI_OFF (2 * 128 * AST * 2)
#define B_LO_OFF (3 * 128 * AST * 2)
#define PROJ_SMEM (4 * 128 * AST * 2)

__global__ __launch_bounds__(256) void proj_mma_kernel(const float* __restrict__ x)
{
    extern __shared__ __align__(16) char smem[];
    const int tid  = threadIdx.x;
    const int wid  = tid >> 5;
    const int lane = tid & 31;
    const int wm   = wid >> 2;
    const int wn   = wid & 3;
    const int g    = lane >> 2;
    const int q    = lane & 3;
    const int row0 = blockIdx.x * 128;
    const int o    = blockIdx.y;

    const __nv_bfloat16* wt_hi = g_wt[o * 2 + 0];
    const __nv_bfloat16* wt_lo = g_wt[o * 2 + 1];

    float acc[4][4][4];
#pragma unroll
    for (int m = 0; m < 4; m++)
#pragma unroll
        for (int n = 0; n < 4; n++)
#pragma unroll
            for (int r = 0; r < 4; r++) acc[m][n][r] = 0.f;

    for (int s = 0; s < 16; s++) {
        const int k0 = s * 64;
        __syncthreads();

#pragma unroll
        for (int i = 0; i < 8; i++) {
            int u = tid + 256 * i;
            int r = u >> 4, gg = u & 15;
            float4 f = *(const float4*)(x + (size_t)(row0 + r) * C_ + k0 + gg * 4);
            __nv_bfloat16 h0 = __float2bfloat16(f.x);
            __nv_bfloat16 h1 = __float2bfloat16(f.y);
            __nv_bfloat16 h2 = __float2bfloat16(f.z);
            __nv_bfloat16 h3 = __float2bfloat16(f.w);
            __nv_bfloat162 hA = __halves2bfloat162(h0, h1);
            __nv_bfloat162 hB = __halves2bfloat162(h2, h3);
            __nv_bfloat162 lA = __halves2bfloat162(
                __float2bfloat16(f.x - __bfloat162float(h0)),
                __float2bfloat16(f.y - __bfloat162float(h1)));
            __nv_bfloat162 lB = __halves2bfloat162(
                __float2bfloat16(f.z - __bfloat162float(h2)),
                __float2bfloat16(f.w - __bfloat162float(h3)));
            uint32_t off = (uint32_t)(r * (AST * 2) + gg * 8);
            *(uint2*)(smem + A_HI_OFF + off) =
                make_uint2(*(uint32_t*)&hA, *(uint32_t*)&hB);
            *(uint2*)(smem + A_LO_OFF + off) =
                make_uint2(*(uint32_t*)&lA, *(uint32_t*)&lB);
        }
#pragma unroll
        for (int i = 0; i < 8; i++) {
            int u = tid + 256 * i;
            int t = u >> 10;
            int w = u & 1023;
            int n = w >> 3, gg = w & 7;
            const __nv_bfloat16* src = (t == 0) ? wt_hi : wt_lo;
            uint4 v = *(const uint4*)(src + (size_t)n * C_ + k0 + gg * 8);
            uint32_t off = (uint32_t)(n * (AST * 2) + gg * 16);
            char* dst = smem + ((t == 0) ? B_HI_OFF : B_LO_OFF) + off;
            *(uint2*)(dst + 0) = make_uint2(v.x, v.y);
            *(uint2*)(dst + 8) = make_uint2(v.z, v.w);
        }
        __syncthreads();

#pragma unroll
        for (int p = 0; p < 3; p++) {
            const char* sA = smem + ((p == 2) ? A_LO_OFF : A_HI_OFF);
            const char* sB = smem + ((p == 1) ? B_LO_OFF : B_HI_OFF);
#pragma unroll
            for (int kk = 0; kk < 4; kk++) {
                const uint32_t kb = kk * 32 + q * 4;
                uint32_t af[4][4];
#pragma unroll
                for (int m = 0; m < 4; m++) {
                    const char* ra =
                        sA + (uint32_t)((wm * 64 + m * 16 + g) * (AST * 2)) + kb;
                    af[m][0] = *(const uint32_t*)(ra);
                    af[m][1] = *(const uint32_t*)(ra + 8 * (AST * 2));
                    af[m][2] = *(const uint32_t*)(ra + 16);
                    af[m][3] = *(const uint32_t*)(ra + 8 * (AST * 2) + 16);
                }
                uint32_t bf[4][2];
#pragma unroll
                for (int n = 0; n < 4; n++) {
                    const char* rb =
                        sB + (uint32_t)((wn * 32 + n * 8 + g) * (AST * 2)) + kb;
                    bf[n][0] = *(const uint32_t*)(rb);
                    bf[n][1] = *(const uint32_t*)(rb + 16);
                }
#pragma unroll
                for (int m = 0; m < 4; m++)
#pragma unroll
                    for (int n = 0; n < 4; n++)
                        mma16816(acc[m][n], af[m], bf[n]);
            }
        }
    }

    const float sc = (o == 1) ? 0.03125f : 1.0f;
    __nv_bfloat16* dh = (o == 0) ? g_kh : (o == 1) ? g_qh : g_vh;
    __nv_bfloat16* dl = (o == 0) ? g_kl : (o == 1) ? g_ql : g_vl;
#pragma unroll
    for (int m = 0; m < 4; m++) {
        int r0 = row0 + wm * 64 + m * 16 + g;
#pragma unroll
        for (int n = 0; n < 4; n++) {
            int col = wn * 32 + n * 8 + q * 2;
            float v0 = acc[m][n][0] * sc, v1 = acc[m][n][1] * sc;
            float v2 = acc[m][n][2] * sc, v3 = acc[m][n][3] * sc;
            __nv_bfloat16 h0 = __float2bfloat16(v0), h1 = __float2bfloat16(v1);
            __nv_bfloat16 h2 = __float2bfloat16(v2), h3 = __float2bfloat16(v3);
            *(uint32_t*)(dh + (size_t)r0 * H_ + col) =
                pack_bf16(__bfloat162float(h0), __bfloat162float(h1));
            *(uint32_t*)(dl + (size_t)r0 * H_ + col) =
                pack_bf16(v0 - __bfloat162float(h0), v1 - __bfloat162float(h1));
            *(uint32_t*)(dh + (size_t)(r0 + 8) * H_ + col) =
                pack_bf16(__bfloat162float(h2), __bfloat162float(h3));
            *(uint32_t*)(dl + (size_t)(r0 + 8) * H_ + col) =
                pack_bf16(v2 - __bfloat162float(h2), v3 - __bfloat162float(h3));
        }
    }
}

// ---------------------------------------------------------------------------
// Kernel 2: causal flash attention — two INDEPENDENT warp-groups per CTA,
// balanced 33/33 chunk split (32-kv chunks), per-group cp.async double
// buffers + named barriers, end-of-kernel split-KV merge for tile B.
//   group0 (warps 0-3):  tile qtB = 31-p, chunks c = 0..32
//   group1 (warps 4-7):  tile qtA = p, chunks 0..2p+1; then HELPER on tile
//                        qtB, chunks 33..63-2p.  Both groups: 33 chunks.
// ---------------------------------------------------------------------------
#define QKS 272
#define TSZ (64 * QKS)          // 17408
#define HTSZ (32 * QKS)         // 8704  (one 32-row array)
#define BUFSZ (4 * HTSZ)        // 34816 (Kh,Kl,Vh,Vl)
#define QBH_OFF 0
#define QBL_OFF (1 * TSZ)
#define QAH_OFF (2 * TSZ)
#define QAL_OFF (3 * TSZ)
#define KV0_OFF (4 * TSZ)       // 4 bufs: grp*2 + parity
#define MRG_O   (KV0_OFF + 2 * BUFSZ)       // reuse grp1 buf0: 64 x 132 f32
#define MRG_M   (MRG_O + 64 * 132 * 4)
#define MRG_L   (MRG_M + 256)
#define ATTN_SMEM (12 * TSZ)    // 208896

__global__ __launch_bounds__(256) void attn_mma_kernel(float* __restrict__ out)
{
    extern __shared__ __align__(16) char smem[];
    const uint32_t sb = cvta_sm(smem);
    const int tid  = threadIdx.x;
    const int w    = tid >> 5;
    const int grp  = tid >> 7;        // 0: tile-B group, 1: tile-A(+helper)
    const int wl   = w & 3;
    const int lane = tid & 31;
    const int g    = lane >> 2;
    const int q4   = lane & 3;
    const int tid128 = tid & 127;

    const int b   = blockIdx.x >> 4;
    const int p   = blockIdx.x & 15;
    const int qtA = p, qtB = 31 - p;
    const int bT  = b * T_;
    const int nOwn = (grp == 0) ? 33 : (2 * p + 2);

    const uint32_t lm_off = (uint32_t)((lane & 15) * QKS + (lane >> 4) * 16);

    // ---- Stage both Q tiles cooperatively (256 threads), then full sync ----
#pragma unroll
    for (int i = 0; i < 8; i++) {
        int u = tid + 256 * i;
        int t = u >> 10;                 // 0 = tile B, 1 = tile A
        int rem = u & 1023;
        int r = rem >> 4, c = rem & 15;
        int qrow = (t == 0 ? qtB : qtA) * 64 + r;
        size_t src = (size_t)(bT + qrow) * H_ + c * 8;
        uint32_t dst = (uint32_t)(t * 2 * TSZ + r * QKS + c * 16);
        *(uint4*)(smem + QBH_OFF + dst) = *(const uint4*)(g_qh + src);
        *(uint4*)(smem + QBL_OFF + dst) = *(const uint4*)(g_ql + src);
    }
    __syncthreads();

    // chunk staging (group-local, 128 threads, 16 CP16 each)
#define STAGE_CHUNK(ckv, dstb) do {                                          \
    _Pragma("unroll")                                                        \
    for (int ii = 0; ii < 16; ii++) {                                        \
        int u = tid128 + 128 * ii;                                           \
        int t = u >> 9; int rem = u & 511;                                   \
        int r = rem >> 4, cc = rem & 15;                                     \
        size_t srco = (size_t)(bT + 32 * (ckv) + r) * H_ + cc * 8;           \
        const __nv_bfloat16* sp = (t == 0) ? g_kh : (t == 1) ? g_kl          \
                                 : (t == 2) ? g_vh : g_vl;                   \
        CP16((dstb) + (uint32_t)(t * HTSZ + r * QKS + cc * 16), sp + srco);  \
    } } while (0)

    // Prologue: both groups' first chunk is kv chunk 0 (own tile).
    STAGE_CHUNK(0, sb + KV0_OFF + (uint32_t)(grp * 2) * BUFSZ);
    CP_COMMIT();

    float oacc[16][4];
#pragma unroll
    for (int n = 0; n < 16; n++)
#pragma unroll
        for (int r = 0; r < 4; r++) oacc[n][r] = 0.f;
    float m0 = -1e30f, m1 = -1e30f, l0 = 0.f, l1 = 0.f;

    for (int i = 0; i < 33; i++) {
        // group A: flush its finished own tile, reset state for helper work
        if (grp == 1 && i == nOwn) {
            float i0 = 1.f / l0, i1 = 1.f / l1;
            size_t rbase = (size_t)(bT + qtA * 64 + wl * 16 + g);
#pragma unroll
            for (int n = 0; n < 16; n++) {
                int col = n * 8 + q4 * 2;
                *(float2*)(out + rbase * H_ + col) =
                    make_float2(oacc[n][0] * i0, oacc[n][1] * i0);
                *(float2*)(out + (rbase + 8) * H_ + col) =
                    make_float2(oacc[n][2] * i1, oacc[n][3] * i1);
            }
#pragma unroll
            for (int n = 0; n < 16; n++)
#pragma unroll
                for (int r = 0; r < 4; r++) oacc[n][r] = 0.f;
            m0 = m1 = -1e30f; l0 = l1 = 0.f;
        }

        BARG(grp + 1);   // group done computing from buf (i+1)&1's old data

        if (i + 1 < 33) {
            int cn = (grp == 0) ? (i + 1)
                   : ((i + 1 < nOwn) ? (i + 1) : 33 + (i + 1 - nOwn));
            STAGE_CHUNK(cn, sb + KV0_OFF +
                        (uint32_t)(grp * 2 + ((i + 1) & 1)) * BUFSZ);
        }
        CP_COMMIT();
        CP_WAIT1();      // chunk i ready
        BARG(grp + 1);

        const int own = (grp == 1 && i < nOwn);
        const int tile_qt = own ? qtA : qtB;
        const int c = (grp == 0) ? i : (own ? i : 33 + (i - nOwn));
        const uint32_t kvb = (uint32_t)(KV0_OFF + (grp * 2 + (i & 1)) * BUFSZ);
        const uint32_t qh_off = own ? QAH_OFF : QBH_OFF;
        const uint32_t ql_off = qh_off + TSZ;

        // ---- S = Q K^T over 64q x 32kv, 3 split passes ----
        float sacc[4][4];
#pragma unroll
        for (int n = 0; n < 4; n++)
#pragma unroll
            for (int r = 0; r < 4; r++) sacc[n][r] = 0.f;

        const uint32_t qrow_off = (uint32_t)(wl * 16 * QKS);
#pragma unroll
        for (int ps = 0; ps < 3; ps++) {
            const uint32_t qb = sb + ((ps == 2) ? ql_off : qh_off) + qrow_off + lm_off;
            const uint32_t kb = sb + kvb + ((ps == 1) ? HTSZ : 0) + lm_off;
#pragma unroll
            for (int kt = 0; kt < 8; kt++) {
                uint32_t a[4];
                LDSM_X4(a[0], a[1], a[2], a[3], qb + kt * 32);
#pragma unroll
                for (int nq = 0; nq < 2; nq++) {
                    uint32_t r0, r1, r2, r3;
                    LDSM_X4(r0, r1, r2, r3, kb + nq * 16 * QKS + kt * 32);
                    uint32_t b0[2] = {r0, r2}, b1[2] = {r1, r3};
                    mma16816(sacc[nq * 2], a, b0);
                    mma16816(sacc[nq * 2 + 1], a, b1);
                }
            }
        }

        // ---- generic causal mask: col 32c+cl > row 64qt+rl ----
        if (32 * c + 31 > 64 * tile_qt) {
            int dd = 64 * tile_qt - 32 * c;
            int rl0 = wl * 16 + g + dd, rl1 = rl0 + 8;
#pragma unroll
            for (int n = 0; n < 4; n++) {
                int cb = n * 8 + q4 * 2;
                if (cb     > rl0) sacc[n][0] = -1e30f;
                if (cb + 1 > rl0) sacc[n][1] = -1e30f;
                if (cb     > rl1) sacc[n][2] = -1e30f;
                if (cb + 1 > rl1) sacc[n][3] = -1e30f;
            }
        }

        // ---- online softmax ----
        float mx0 = -1e30f, mx1 = -1e30f;
#pragma unroll
        for (int n = 0; n < 4; n++) {
            mx0 = fmaxf(mx0, fmaxf(sacc[n][0], sacc[n][1]));
            mx1 = fmaxf(mx1, fmaxf(sacc[n][2], sacc[n][3]));
        }
        mx0 = fmaxf(mx0, __shfl_xor_sync(0xffffffffu, mx0, 1));
        mx0 = fmaxf(mx0, __shfl_xor_sync(0xffffffffu, mx0, 2));
        mx1 = fmaxf(mx1, __shfl_xor_sync(0xffffffffu, mx1, 1));
        mx1 = fmaxf(mx1, __shfl_xor_sync(0xffffffffu, mx1, 2));
        float mn0 = fmaxf(m0, mx0), mn1 = fmaxf(m1, mx1);
        float c0 = __expf(m0 - mn0), c1 = __expf(m1 - mn1);
        m0 = mn0; m1 = mn1;

        uint32_t ph[4][2], pl[4][2];
        float s0 = 0.f, s1 = 0.f;
#pragma unroll
        for (int n = 0; n < 4; n++) {
            float p00 = __expf(sacc[n][0] - mn0);
            float p01 = __expf(sacc[n][1] - mn0);
            float p10 = __expf(sacc[n][2] - mn1);
            float p11 = __expf(sacc[n][3] - mn1);
            s0 += p00 + p01; s1 += p10 + p11;
            __nv_bfloat16 h00 = __float2bfloat16(p00);
            __nv_bfloat16 h01 = __float2bfloat16(p01);
            __nv_bfloat16 h10 = __float2bfloat16(p10);
            __nv_bfloat16 h11 = __float2bfloat16(p11);
            ph[n][0] = pack_bf16(__bfloat162float(h00), __bfloat162float(h01));
            ph[n][1] = pack_bf16(__bfloat162float(h10), __bfloat162float(h11));
            pl[n][0] = pack_bf16(p00 - __bfloat162float(h00),
                                 p01 - __bfloat162float(h01));
            pl[n][1] = pack_bf16(p10 - __bfloat162float(h10),
                                 p11 - __bfloat162float(h11));
        }
        s0 += __shfl_xor_sync(0xffffffffu, s0, 1);
        s0 += __shfl_xor_sync(0xffffffffu, s0, 2);
        s1 += __shfl_xor_sync(0xffffffffu, s1, 1);
        s1 += __shfl_xor_sync(0xffffffffu, s1, 2);
        l0 = l0 * c0 + s0;
        l1 = l1 * c1 + s1;
#pragma unroll
        for (int n = 0; n < 16; n++) {
            oacc[n][0] *= c0; oacc[n][1] *= c0;
            oacc[n][2] *= c1; oacc[n][3] *= c1;
        }

        // ---- O += P V over 32 kv, 3 split passes ----
#pragma unroll
        for (int ps = 0; ps < 3; ps++) {
            const uint32_t vb = sb + kvb + ((ps == 1) ? 3 : 2) * HTSZ + lm_off;
            const uint32_t (*P)[2] = (ps == 2) ? pl : ph;
#pragma unroll
            for (int kt = 0; kt < 2; kt++) {
                uint32_t a[4];
                a[0] = P[2 * kt][0];
                a[1] = P[2 * kt][1];
                a[2] = P[2 * kt + 1][0];
                a[3] = P[2 * kt + 1][1];
#pragma unroll
                for (int np = 0; np < 8; np++) {
                    uint32_t r0, r1, r2, r3;
                    LDSM_X4_T(r0, r1, r2, r3,
                              vb + (uint32_t)(kt * 16 * QKS) + np * 32);
                    uint32_t b0[2] = {r0, r1}, b1[2] = {r2, r3};
                    mma16816(oacc[np * 2], a, b0);
                    mma16816(oacc[np * 2 + 1], a, b1);
                }
            }
        }
    }

    // ---- group A: publish tile-B partial (O, m, l) to smem ----
    if (grp == 1) {
        BARG(2);   // all A-warps done reading their buffers
        float* Osm = (float*)(smem + MRG_O);
        float* Msm = (float*)(smem + MRG_M);
        float* Lsm = (float*)(smem + MRG_L);
        int r0 = wl * 16 + g, r1 = r0 + 8;
#pragma unroll
        for (int n = 0; n < 16; n++) {
            int col = n * 8 + q4 * 2;
            *(float2*)&Osm[r0 * 132 + col] = make_float2(oacc[n][0], oacc[n][1]);
            *(float2*)&Osm[r1 * 132 + col] = make_float2(oacc[n][2], oacc[n][3]);
        }
        if (q4 == 0) {
            Msm[r0] = m0; Lsm[r0] = l0;
            Msm[r1] = m1; Lsm[r1] = l1;
        }
    }
    __syncthreads();

    // ---- group B: merge partials and write tile-B output ----
    if (grp == 0) {
        float* Osm = (float*)(smem + MRG_O);
        float* Msm = (float*)(smem + MRG_M);
        float* Lsm = (float*)(smem + MRG_L);
        int r0 = wl * 16 + g, r1 = r0 + 8;
        float mA0 = Msm[r0], lA0 = Lsm[r0];
        float mA1 = Msm[r1], lA1 = Lsm[r1];
        float nm0 = fmaxf(m0, mA0), nm1 = fmaxf(m1, mA1);
        float sB0 = __expf(m0 - nm0), sA0 = __expf(mA0 - nm0);
        float sB1 = __expf(m1 - nm1), sA1 = __expf(mA1 - nm1);
        l0 = l0 * sB0 + lA0 * sA0;
        l1 = l1 * sB1 + lA1 * sA1;
        float i0 = 1.f / l0, i1 = 1.f / l1;
        size_t rbase = (size_t)(bT + qtB * 64 + wl * 16 + g);
#pragma unroll
        for (int n = 0; n < 16; n++) {
            int col = n * 8 + q4 * 2;
            float2 pa0 = *(float2*)&Osm[r0 * 132 + col];
            float2 pa1 = *(float2*)&Osm[r1 * 132 + col];
            *(float2*)(out + rbase * H_ + col) = make_float2(
                (oacc[n][0] * sB0 + pa0.x * sA0) * i0,
                (oacc[n][1] * sB0 + pa0.y * sA0) * i0);
            *(float2*)(out + (rbase + 8) * H_ + col) = make_float2(
                (oacc[n][2] * sB1 + pa1.x * sA1) * i1,
                (oacc[n][3] * sB1 + pa1.y * sA1) * i1);
        }
    }
}

// ---------------------------------------------------------------------------
extern "C" void kernel_launch(void* const* d_in, const int* in_sizes, int n_in,
                              void* d_out, int out_size)
{
    const float* x  = (const float*)d_in[0];
    const float* Wk = (const float*)d_in[1];
    const float* Wq = (const float*)d_in[2];
    const float* Wv = (const float*)d_in[3];
    float* out = (float*)d_out;

    cudaFuncSetAttribute(proj_mma_kernel,
                         cudaFuncAttributeMaxDynamicSharedMemorySize, PROJ_SMEM);
    cudaFuncSetAttribute(attn_mma_kernel,
                         cudaFuncAttributeMaxDynamicSharedMemorySize, ATTN_SMEM);

    wsplit_kernel<<<dim3(512, 3), 256>>>(Wk, Wq, Wv);
    proj_mma_kernel<<<dim3(128, 3), 256, PROJ_SMEM>>>(x);
    attn_mma_kernel<<<128, 256, ATTN_SMEM>>>(out);
}

// round 13
// speedup vs baseline: 1.1860x; 1.0007x over previous
#include <cuda_runtime.h>
#include <cuda_bf16.h>
#include <cstdint>
#include <math.h>

// Problem shape (fixed by the reference).
#define B_ 8
#define T_ 2048
#define C_ 1024
#define H_ 128
#define M_ (B_ * T_)

// Scratch (no cudaMalloc -> __device__ globals).
__device__ __align__(16) __nv_bfloat16 g_qh[(size_t)M_ * H_];
__device__ __align__(16) __nv_bfloat16 g_ql[(size_t)M_ * H_];
__device__ __align__(16) __nv_bfloat16 g_kh[(size_t)M_ * H_];
__device__ __align__(16) __nv_bfloat16 g_kl[(size_t)M_ * H_];
__device__ __align__(16) __nv_bfloat16 g_vh[(size_t)M_ * H_];
__device__ __align__(16) __nv_bfloat16 g_vl[(size_t)M_ * H_];
__device__ __align__(16) __nv_bfloat16 g_wt[6][128 * 1024];

__device__ __forceinline__ uint32_t pack_bf16(float a, float b) {
    __nv_bfloat162 t = __halves2bfloat162(__float2bfloat16(a), __float2bfloat16(b));
    return *(uint32_t*)&t;
}

__device__ __forceinline__ void mma16816(float* d, const uint32_t* a,
                                         const uint32_t* b) {
    asm volatile(
        "mma.sync.aligned.m16n8k16.row.col.f32.bf16.bf16.f32 "
        "{%0,%1,%2,%3}, {%4,%5,%6,%7}, {%8,%9}, {%0,%1,%2,%3};"
        : "+f"(d[0]), "+f"(d[1]), "+f"(d[2]), "+f"(d[3])
        : "r"(a[0]), "r"(a[1]), "r"(a[2]), "r"(a[3]), "r"(b[0]), "r"(b[1]));
}

__device__ __forceinline__ uint32_t cvta_sm(const void* p) {
    uint32_t a;
    asm("{ .reg .u64 t; cvta.to.shared.u64 t, %1; cvt.u32.u64 %0, t; }"
        : "=r"(a) : "l"(p));
    return a;
}
#define LDSM_X4(r0, r1, r2, r3, a)                                        \
    asm volatile("ldmatrix.sync.aligned.m8n8.x4.shared.b16 "              \
                 "{%0,%1,%2,%3}, [%4];"                                   \
                 : "=r"(r0), "=r"(r1), "=r"(r2), "=r"(r3) : "r"(a))
#define LDSM_X4_T(r0, r1, r2, r3, a)                                      \
    asm volatile("ldmatrix.sync.aligned.m8n8.x4.trans.shared.b16 "        \
                 "{%0,%1,%2,%3}, [%4];"                                   \
                 : "=r"(r0), "=r"(r1), "=r"(r2), "=r"(r3) : "r"(a))
#define CP16(dst, src)                                                    \
    asm volatile("cp.async.cg.shared.global [%0], [%1], 16;"              \
                 :: "r"(dst), "l"(src))
#define CP_COMMIT() asm volatile("cp.async.commit_group;" ::: "memory")
#define CP_WAIT1()  asm volatile("cp.async.wait_group 1;"  ::: "memory")
#define BARG(id)                                                          \
    asm volatile("bar.sync %0, %1;" :: "r"(id), "r"(128) : "memory")

// ---------------------------------------------------------------------------
// Kernel 0: split + transpose weights into bf16 hi/lo, K-major [n][k].
// ---------------------------------------------------------------------------
__global__ __launch_bounds__(256) void wsplit_kernel(
    const float* __restrict__ Wk, const float* __restrict__ Wq,
    const float* __restrict__ Wv)
{
    int o = blockIdx.y;
    const float* W = (o == 0) ? Wk : (o == 1) ? Wq : Wv;
    int idx = blockIdx.x * 256 + threadIdx.x;
    int n = idx >> 10, k = idx & 1023;
    float v = W[(size_t)k * H_ + n];
    __nv_bfloat16 hi = __float2bfloat16(v);
    float lo = v - __bfloat162float(hi);
    g_wt[o * 2 + 0][idx] = hi;
    g_wt[o * 2 + 1][idx] = __float2bfloat16(lo);
}

// ---------------------------------------------------------------------------
// Kernel 1: QKV projection (EXACT R10 version: scalar-LDS fragments, proven).
// ---------------------------------------------------------------------------
#define AST 72
#define A_HI_OFF 0
#define A_LO_OFF (128 * AST * 2)
#define B_HI_OFF (2 * 128 * AST * 2)
#define B_LO_OFF (3 * 128 * AST * 2)
#define PROJ_SMEM (4 * 128 * AST * 2)

__global__ __launch_bounds__(256) void proj_mma_kernel(const float* __restrict__ x)
{
    extern __shared__ __align__(16) char smem[];
    const int tid  = threadIdx.x;
    const int wid  = tid >> 5;
    const int lane = tid & 31;
    const int wm   = wid >> 2;
    const int wn   = wid & 3;
    const int g    = lane >> 2;
    const int q    = lane & 3;
    const int row0 = blockIdx.x * 128;
    const int o    = blockIdx.y;

    const __nv_bfloat16* wt_hi = g_wt[o * 2 + 0];
    const __nv_bfloat16* wt_lo = g_wt[o * 2 + 1];

    float acc[4][4][4];
#pragma unroll
    for (int m = 0; m < 4; m++)
#pragma unroll
        for (int n = 0; n < 4; n++)
#pragma unroll
            for (int r = 0; r < 4; r++) acc[m][n][r] = 0.f;

    for (int s = 0; s < 16; s++) {
        const int k0 = s * 64;
        __syncthreads();

#pragma unroll
        for (int i = 0; i < 8; i++) {
            int u = tid + 256 * i;
            int r = u >> 4, gg = u & 15;
            float4 f = *(const float4*)(x + (size_t)(row0 + r) * C_ + k0 + gg * 4);
            __nv_bfloat16 h0 = __float2bfloat16(f.x);
            __nv_bfloat16 h1 = __float2bfloat16(f.y);
            __nv_bfloat16 h2 = __float2bfloat16(f.z);
            __nv_bfloat16 h3 = __float2bfloat16(f.w);
            __nv_bfloat162 hA = __halves2bfloat162(h0, h1);
            __nv_bfloat162 hB = __halves2bfloat162(h2, h3);
            __nv_bfloat162 lA = __halves2bfloat162(
                __float2bfloat16(f.x - __bfloat162float(h0)),
                __float2bfloat16(f.y - __bfloat162float(h1)));
            __nv_bfloat162 lB = __halves2bfloat162(
                __float2bfloat16(f.z - __bfloat162float(h2)),
                __float2bfloat16(f.w - __bfloat162float(h3)));
            uint32_t off = (uint32_t)(r * (AST * 2) + gg * 8);
            *(uint2*)(smem + A_HI_OFF + off) =
                make_uint2(*(uint32_t*)&hA, *(uint32_t*)&hB);
            *(uint2*)(smem + A_LO_OFF + off) =
                make_uint2(*(uint32_t*)&lA, *(uint32_t*)&lB);
        }
#pragma unroll
        for (int i = 0; i < 8; i++) {
            int u = tid + 256 * i;
            int t = u >> 10;
            int w = u & 1023;
            int n = w >> 3, gg = w & 7;
            const __nv_bfloat16* src = (t == 0) ? wt_hi : wt_lo;
            uint4 v = *(const uint4*)(src + (size_t)n * C_ + k0 + gg * 8);
            uint32_t off = (uint32_t)(n * (AST * 2) + gg * 16);
            char* dst = smem + ((t == 0) ? B_HI_OFF : B_LO_OFF) + off;
            *(uint2*)(dst + 0) = make_uint2(v.x, v.y);
            *(uint2*)(dst + 8) = make_uint2(v.z, v.w);
        }
        __syncthreads();

#pragma unroll
        for (int p = 0; p < 3; p++) {
            const char* sA = smem + ((p == 2) ? A_LO_OFF : A_HI_OFF);
            const char* sB = smem + ((p == 1) ? B_LO_OFF : B_HI_OFF);
#pragma unroll
            for (int kk = 0; kk < 4; kk++) {
                const uint32_t kb = kk * 32 + q * 4;
                uint32_t af[4][4];
#pragma unroll
                for (int m = 0; m < 4; m++) {
                    const char* ra =
                        sA + (uint32_t)((wm * 64 + m * 16 + g) * (AST * 2)) + kb;
                    af[m][0] = *(const uint32_t*)(ra);
                    af[m][1] = *(const uint32_t*)(ra + 8 * (AST * 2));
                    af[m][2] = *(const uint32_t*)(ra + 16);
                    af[m][3] = *(const uint32_t*)(ra + 8 * (AST * 2) + 16);
                }
                uint32_t bf[4][2];
#pragma unroll
                for (int n = 0; n < 4; n++) {
                    const char* rb =
                        sB + (uint32_t)((wn * 32 + n * 8 + g) * (AST * 2)) + kb;
                    bf[n][0] = *(const uint32_t*)(rb);
                    bf[n][1] = *(const uint32_t*)(rb + 16);
                }
#pragma unroll
                for (int m = 0; m < 4; m++)
#pragma unroll
                    for (int n = 0; n < 4; n++)
                        mma16816(acc[m][n], af[m], bf[n]);
            }
        }
    }

    const float sc = (o == 1) ? 0.03125f : 1.0f;
    __nv_bfloat16* dh = (o == 0) ? g_kh : (o == 1) ? g_qh : g_vh;
    __nv_bfloat16* dl = (o == 0) ? g_kl : (o == 1) ? g_ql : g_vl;
#pragma unroll
    for (int m = 0; m < 4; m++) {
        int r0 = row0 + wm * 64 + m * 16 + g;
#pragma unroll
        for (int n = 0; n < 4; n++) {
            int col = wn * 32 + n * 8 + q * 2;
            float v0 = acc[m][n][0] * sc, v1 = acc[m][n][1] * sc;
            float v2 = acc[m][n][2] * sc, v3 = acc[m][n][3] * sc;
            __nv_bfloat16 h0 = __float2bfloat16(v0), h1 = __float2bfloat16(v1);
            __nv_bfloat16 h2 = __float2bfloat16(v2), h3 = __float2bfloat16(v3);
            *(uint32_t*)(dh + (size_t)r0 * H_ + col) =
                pack_bf16(__bfloat162float(h0), __bfloat162float(h1));
            *(uint32_t*)(dl + (size_t)r0 * H_ + col) =
                pack_bf16(v0 - __bfloat162float(h0), v1 - __bfloat162float(h1));
            *(uint32_t*)(dh + (size_t)(r0 + 8) * H_ + col) =
                pack_bf16(__bfloat162float(h2), __bfloat162float(h3));
            *(uint32_t*)(dl + (size_t)(r0 + 8) * H_ + col) =
                pack_bf16(v2 - __bfloat162float(h2), v3 - __bfloat162float(h3));
        }
    }
}

// ---------------------------------------------------------------------------
// Kernel 2: causal flash attention — two INDEPENDENT warp-groups per CTA,
// balanced 33/33 chunk split (32-kv chunks), per-group cp.async double
// buffers + named barriers, end-of-kernel split-KV merge for tile B.
//   group0 (warps 0-3):  tile qtB = 31-p, chunks c = 0..32
//   group1 (warps 4-7):  tile qtA = p, chunks 0..2p+1; then HELPER on tile
//                        qtB, chunks 33..63-2p.  Both groups: 33 chunks.
// ---------------------------------------------------------------------------
#define QKS 272
#define TSZ (64 * QKS)          // 17408
#define HTSZ (32 * QKS)         // 8704  (one 32-row array)
#define BUFSZ (4 * HTSZ)        // 34816 (Kh,Kl,Vh,Vl)
#define QBH_OFF 0
#define QBL_OFF (1 * TSZ)
#define QAH_OFF (2 * TSZ)
#define QAL_OFF (3 * TSZ)
#define KV0_OFF (4 * TSZ)       // 4 bufs: grp*2 + parity
#define MRG_O   (KV0_OFF + 2 * BUFSZ)       // reuse grp1 buf0: 64 x 132 f32
#define MRG_M   (MRG_O + 64 * 132 * 4)
#define MRG_L   (MRG_M + 256)
#define ATTN_SMEM (12 * TSZ)    // 208896

__global__ __launch_bounds__(256) void attn_mma_kernel(float* __restrict__ out)
{
    extern __shared__ __align__(16) char smem[];
    const uint32_t sb = cvta_sm(smem);
    const int tid  = threadIdx.x;
    const int w    = tid >> 5;
    const int grp  = tid >> 7;        // 0: tile-B group, 1: tile-A(+helper)
    const int wl   = w & 3;
    const int lane = tid & 31;
    const int g    = lane >> 2;
    const int q4   = lane & 3;
    const int tid128 = tid & 127;

    const int b   = blockIdx.x >> 4;
    const int p   = blockIdx.x & 15;
    const int qtA = p, qtB = 31 - p;
    const int bT  = b * T_;
    const int nOwn = (grp == 0) ? 33 : (2 * p + 2);

    const uint32_t lm_off = (uint32_t)((lane & 15) * QKS + (lane >> 4) * 16);

    // ---- Stage both Q tiles cooperatively (256 threads), then full sync ----
#pragma unroll
    for (int i = 0; i < 8; i++) {
        int u = tid + 256 * i;
        int t = u >> 10;                 // 0 = tile B, 1 = tile A
        int rem = u & 1023;
        int r = rem >> 4, c = rem & 15;
        int qrow = (t == 0 ? qtB : qtA) * 64 + r;
        size_t src = (size_t)(bT + qrow) * H_ + c * 8;
        uint32_t dst = (uint32_t)(t * 2 * TSZ + r * QKS + c * 16);
        *(uint4*)(smem + QBH_OFF + dst) = *(const uint4*)(g_qh + src);
        *(uint4*)(smem + QBL_OFF + dst) = *(const uint4*)(g_ql + src);
    }
    __syncthreads();

    // chunk staging (group-local, 128 threads, 16 CP16 each)
#define STAGE_CHUNK(ckv, dstb) do {                                          \
    _Pragma("unroll")                                                        \
    for (int ii = 0; ii < 16; ii++) {                                        \
        int u = tid128 + 128 * ii;                                           \
        int t = u >> 9; int rem = u & 511;                                   \
        int r = rem >> 4, cc = rem & 15;                                     \
        size_t srco = (size_t)(bT + 32 * (ckv) + r) * H_ + cc * 8;           \
        const __nv_bfloat16* sp = (t == 0) ? g_kh : (t == 1) ? g_kl          \
                                 : (t == 2) ? g_vh : g_vl;                   \
        CP16((dstb) + (uint32_t)(t * HTSZ + r * QKS + cc * 16), sp + srco);  \
    } } while (0)

    // Prologue: both groups' first chunk is kv chunk 0 (own tile).
    STAGE_CHUNK(0, sb + KV0_OFF + (uint32_t)(grp * 2) * BUFSZ);
    CP_COMMIT();

    float oacc[16][4];
#pragma unroll
    for (int n = 0; n < 16; n++)
#pragma unroll
        for (int r = 0; r < 4; r++) oacc[n][r] = 0.f;
    float m0 = -1e30f, m1 = -1e30f, l0 = 0.f, l1 = 0.f;

    for (int i = 0; i < 33; i++) {
        // group A: flush its finished own tile, reset state for helper work
        if (grp == 1 && i == nOwn) {
            float i0 = 1.f / l0, i1 = 1.f / l1;
            size_t rbase = (size_t)(bT + qtA * 64 + wl * 16 + g);
#pragma unroll
            for (int n = 0; n < 16; n++) {
                int col = n * 8 + q4 * 2;
                *(float2*)(out + rbase * H_ + col) =
                    make_float2(oacc[n][0] * i0, oacc[n][1] * i0);
                *(float2*)(out + (rbase + 8) * H_ + col) =
                    make_float2(oacc[n][2] * i1, oacc[n][3] * i1);
            }
#pragma unroll
            for (int n = 0; n < 16; n++)
#pragma unroll
                for (int r = 0; r < 4; r++) oacc[n][r] = 0.f;
            m0 = m1 = -1e30f; l0 = l1 = 0.f;
        }

        BARG(grp + 1);   // group done computing from buf (i+1)&1's old data

        if (i + 1 < 33) {
            int cn = (grp == 0) ? (i + 1)
                   : ((i + 1 < nOwn) ? (i + 1) : 33 + (i + 1 - nOwn));
            STAGE_CHUNK(cn, sb + KV0_OFF +
                        (uint32_t)(grp * 2 + ((i + 1) & 1)) * BUFSZ);
        }
        CP_COMMIT();
        CP_WAIT1();      // chunk i ready
        BARG(grp + 1);

        const int own = (grp == 1 && i < nOwn);
        const int tile_qt = own ? qtA : qtB;
        const int c = (grp == 0) ? i : (own ? i : 33 + (i - nOwn));
        const uint32_t kvb = (uint32_t)(KV0_OFF + (grp * 2 + (i & 1)) * BUFSZ);
        const uint32_t qh_off = own ? QAH_OFF : QBH_OFF;
        const uint32_t ql_off = qh_off + TSZ;

        // ---- S = Q K^T over 64q x 32kv, 3 split passes ----
        float sacc[4][4];
#pragma unroll
        for (int n = 0; n < 4; n++)
#pragma unroll
            for (int r = 0; r < 4; r++) sacc[n][r] = 0.f;

        const uint32_t qrow_off = (uint32_t)(wl * 16 * QKS);
#pragma unroll
        for (int ps = 0; ps < 3; ps++) {
            const uint32_t qb = sb + ((ps == 2) ? ql_off : qh_off) + qrow_off + lm_off;
            const uint32_t kb = sb + kvb + ((ps == 1) ? HTSZ : 0) + lm_off;
#pragma unroll
            for (int kt = 0; kt < 8; kt++) {
                uint32_t a[4];
                LDSM_X4(a[0], a[1], a[2], a[3], qb + kt * 32);
#pragma unroll
                for (int nq = 0; nq < 2; nq++) {
                    uint32_t r0, r1, r2, r3;
                    LDSM_X4(r0, r1, r2, r3, kb + nq * 16 * QKS + kt * 32);
                    uint32_t b0[2] = {r0, r2}, b1[2] = {r1, r3};
                    mma16816(sacc[nq * 2], a, b0);
                    mma16816(sacc[nq * 2 + 1], a, b1);
                }
            }
        }

        // ---- generic causal mask: col 32c+cl > row 64qt+rl ----
        if (32 * c + 31 > 64 * tile_qt) {
            int dd = 64 * tile_qt - 32 * c;
            int rl0 = wl * 16 + g + dd, rl1 = rl0 + 8;
#pragma unroll
            for (int n = 0; n < 4; n++) {
                int cb = n * 8 + q4 * 2;
                if (cb     > rl0) sacc[n][0] = -1e30f;
                if (cb + 1 > rl0) sacc[n][1] = -1e30f;
                if (cb     > rl1) sacc[n][2] = -1e30f;
                if (cb + 1 > rl1) sacc[n][3] = -1e30f;
            }
        }

        // ---- online softmax ----
        float mx0 = -1e30f, mx1 = -1e30f;
#pragma unroll
        for (int n = 0; n < 4; n++) {
            mx0 = fmaxf(mx0, fmaxf(sacc[n][0], sacc[n][1]));
            mx1 = fmaxf(mx1, fmaxf(sacc[n][2], sacc[n][3]));
        }
        mx0 = fmaxf(mx0, __shfl_xor_sync(0xffffffffu, mx0, 1));
        mx0 = fmaxf(mx0, __shfl_xor_sync(0xffffffffu, mx0, 2));
        mx1 = fmaxf(mx1, __shfl_xor_sync(0xffffffffu, mx1, 1));
        mx1 = fmaxf(mx1, __shfl_xor_sync(0xffffffffu, mx1, 2));
        float mn0 = fmaxf(m0, mx0), mn1 = fmaxf(m1, mx1);
        float c0 = __expf(m0 - mn0), c1 = __expf(m1 - mn1);
        m0 = mn0; m1 = mn1;

        uint32_t ph[4][2], pl[4][2];
        float s0 = 0.f, s1 = 0.f;
#pragma unroll
        for (int n = 0; n < 4; n++) {
            float p00 = __expf(sacc[n][0] - mn0);
            float p01 = __expf(sacc[n][1] - mn0);
            float p10 = __expf(sacc[n][2] - mn1);
            float p11 = __expf(sacc[n][3] - mn1);
            s0 += p00 + p01; s1 += p10 + p11;
            __nv_bfloat16 h00 = __float2bfloat16(p00);
            __nv_bfloat16 h01 = __float2bfloat16(p01);
            __nv_bfloat16 h10 = __float2bfloat16(p10);
            __nv_bfloat16 h11 = __float2bfloat16(p11);
            ph[n][0] = pack_bf16(__bfloat162float(h00), __bfloat162float(h01));
            ph[n][1] = pack_bf16(__bfloat162float(h10), __bfloat162float(h11));
            pl[n][0] = pack_bf16(p00 - __bfloat162float(h00),
                                 p01 - __bfloat162float(h01));
            pl[n][1] = pack_bf16(p10 - __bfloat162float(h10),
                                 p11 - __bfloat162float(h11));
        }
        s0 += __shfl_xor_sync(0xffffffffu, s0, 1);
        s0 += __shfl_xor_sync(0xffffffffu, s0, 2);
        s1 += __shfl_xor_sync(0xffffffffu, s1, 1);
        s1 += __shfl_xor_sync(0xffffffffu, s1, 2);
        l0 = l0 * c0 + s0;
        l1 = l1 * c1 + s1;
#pragma unroll
        for (int n = 0; n < 16; n++) {
            oacc[n][0] *= c0; oacc[n][1] *= c0;
            oacc[n][2] *= c1; oacc[n][3] *= c1;
        }

        // ---- O += P V over 32 kv, 3 split passes ----
#pragma unroll
        for (int ps = 0; ps < 3; ps++) {
            const uint32_t vb = sb + kvb + ((ps == 1) ? 3 : 2) * HTSZ + lm_off;
            const uint32_t (*P)[2] = (ps == 2) ? pl : ph;
#pragma unroll
            for (int kt = 0; kt < 2; kt++) {
                uint32_t a[4];
                a[0] = P[2 * kt][0];
                a[1] = P[2 * kt][1];
                a[2] = P[2 * kt + 1][0];
                a[3] = P[2 * kt + 1][1];
#pragma unroll
                for (int np = 0; np < 8; np++) {
                    uint32_t r0, r1, r2, r3;
                    LDSM_X4_T(r0, r1, r2, r3,
                              vb + (uint32_t)(kt * 16 * QKS) + np * 32);
                    uint32_t b0[2] = {r0, r1}, b1[2] = {r2, r3};
                    mma16816(oacc[np * 2], a, b0);
                    mma16816(oacc[np * 2 + 1], a, b1);
                }
            }
        }
    }

    // ---- group A: publish tile-B partial (O, m, l) to smem ----
    if (grp == 1) {
        BARG(2);   // all A-warps done reading their buffers
        float* Osm = (float*)(smem + MRG_O);
        float* Msm = (float*)(smem + MRG_M);
        float* Lsm = (float*)(smem + MRG_L);
        int r0 = wl * 16 + g, r1 = r0 + 8;
#pragma unroll
        for (int n = 0; n < 16; n++) {
            int col = n * 8 + q4 * 2;
            *(float2*)&Osm[r0 * 132 + col] = make_float2(oacc[n][0], oacc[n][1]);
            *(float2*)&Osm[r1 * 132 + col] = make_float2(oacc[n][2], oacc[n][3]);
        }
        if (q4 == 0) {
            Msm[r0] = m0; Lsm[r0] = l0;
            Msm[r1] = m1; Lsm[r1] = l1;
        }
    }
    __syncthreads();

    // ---- group B: merge partials and write tile-B output ----
    if (grp == 0) {
        float* Osm = (float*)(smem + MRG_O);
        float* Msm = (float*)(smem + MRG_M);
        float* Lsm = (float*)(smem + MRG_L);
        int r0 = wl * 16 + g, r1 = r0 + 8;
        float mA0 = Msm[r0], lA0 = Lsm[r0];
        float mA1 = Msm[r1], lA1 = Lsm[r1];
        float nm0 = fmaxf(m0, mA0), nm1 = fmaxf(m1, mA1);
        float sB0 = __expf(m0 - nm0), sA0 = __expf(mA0 - nm0);
        float sB1 = __expf(m1 - nm1), sA1 = __expf(mA1 - nm1);
        l0 = l0 * sB0 + lA0 * sA0;
        l1 = l1 * sB1 + lA1 * sA1;
        float i0 = 1.f / l0, i1 = 1.f / l1;
        size_t rbase = (size_t)(bT + qtB * 64 + wl * 16 + g);
#pragma unroll
        for (int n = 0; n < 16; n++) {
            int col = n * 8 + q4 * 2;
            float2 pa0 = *(float2*)&Osm[r0 * 132 + col];
            float2 pa1 = *(float2*)&Osm[r1 * 132 + col];
            *(float2*)(out + rbase * H_ + col) = make_float2(
                (oacc[n][0] * sB0 + pa0.x * sA0) * i0,
                (oacc[n][1] * sB0 + pa0.y * sA0) * i0);
            *(float2*)(out + (rbase + 8) * H_ + col) = make_float2(
                (oacc[n][2] * sB1 + pa1.x * sA1) * i1,
                (oacc[n][3] * sB1 + pa1.y * sA1) * i1);
        }
    }
}

// ---------------------------------------------------------------------------
extern "C" void kernel_launch(void* const* d_in, const int* in_sizes, int n_in,
                              void* d_out, int out_size)
{
    const float* x  = (const float*)d_in[0];
    const float* Wk = (const float*)d_in[1];
    const float* Wq = (const float*)d_in[2];
    const float* Wv = (const float*)d_in[3];
    float* out = (float*)d_out;

    cudaFuncSetAttribute(proj_mma_kernel,
                         cudaFuncAttributeMaxDynamicSharedMemorySize, PROJ_SMEM);
    cudaFuncSetAttribute(attn_mma_kernel,
                         cudaFuncAttributeMaxDynamicSharedMemorySize, ATTN_SMEM);

    wsplit_kernel<<<dim3(512, 3), 256>>>(Wk, Wq, Wv);
    proj_mma_kernel<<<dim3(128, 3), 256, PROJ_SMEM>>>(x);
    attn_mma_kernel<<<128, 256, ATTN_SMEM>>>(out);
}